// round 15
// baseline (speedup 1.0000x reference)
#include <cuda_runtime.h>
#include <cuda_bf16.h>
#include <cstdint>
#include <math.h>

#define Bn 32
#define Tn 2048
#define Dn 512
#define ZB 32
#define SPLIT 32
#define SEG 16
#define NIT (Tn / 32)

#define NT 16
#define NTILE (NT * (NT + 1) / 2)   // 136 lower cov tiles
#define NBLK 120
#define NTHR 256
#define GTILE 10                    // lower 128x128 tiles of 4x4

// ---------------- static scratch ----------------
__device__ float g_pmean[SEG][Bn][Dn];
__device__ float g_zT[Dn * ZB];                 // z transposed [e][s]
__device__ __nv_bfloat16 g_xcb[(size_t)Bn * Tn * Dn];
__device__ float g_Gpart[SPLIT][Dn * Dn];
__device__ float g_C[Dn * Dn];                  // raw updated covariance (lower tiles)
__device__ float g_L[Dn * Dn];                  // Cholesky factor L (lower)
__device__ unsigned g_bar8[8 * 32];             // distributed barrier counters

__device__ __forceinline__ uint32_t smem_u32(const void* p) {
    return (uint32_t)__cvta_generic_to_shared(p);
}

// grid barrier: distributed arrival (8 lines), relaxed poll, single acquire fence
__device__ __forceinline__ void gbar(unsigned* phase) {
    __syncthreads();
    if (threadIdx.x == 0) {
        unsigned target = (++(*phase)) * NBLK;
        asm volatile("red.release.gpu.add.u32 [%0], 1;"
                     :: "l"(&g_bar8[(blockIdx.x & 7) * 32]) : "memory");
        unsigned s;
        do {
            s = 0;
#pragma unroll
            for (int c = 0; c < 8; c++) {
                unsigned v;
                asm volatile("ld.relaxed.gpu.u32 %0, [%1];"
                             : "=r"(v) : "l"(&g_bar8[c * 32]) : "memory");
                s += v;
            }
        } while (s < target);
        asm volatile("fence.acq_rel.gpu;" ::: "memory");
    }
    __syncthreads();
}

// ---------------- 1) fused partial means + bf16 convert (float4) ------------
__global__ void conv_mean(const float* __restrict__ x) {
    int b   = blockIdx.y;
    int seg = blockIdx.z;
    int tid = threadIdx.x;                    // 128
    int d0  = tid * 4;
    if (b == 0 && seg == 0 && tid < 8) g_bar8[tid * 32] = 0u;
    size_t base = ((size_t)b * Tn + (size_t)seg * (Tn / SEG)) * Dn + d0;
    float s0 = 0.f, s1 = 0.f, s2 = 0.f, s3 = 0.f;
#pragma unroll 8
    for (int t = 0; t < Tn / SEG; t++) {
        float4 v = *(const float4*)(x + base + (size_t)t * Dn);
        s0 += v.x; s1 += v.y; s2 += v.z; s3 += v.w;
        __nv_bfloat162 h0, h1;
        h0.x = __float2bfloat16_rn(v.x);
        h0.y = __float2bfloat16_rn(v.y);
        h1.x = __float2bfloat16_rn(v.z);
        h1.y = __float2bfloat16_rn(v.w);
        uint2 packed;
        packed.x = *(uint32_t*)&h0;
        packed.y = *(uint32_t*)&h1;
        *(uint2*)(g_xcb + base + (size_t)t * Dn) = packed;
    }
    g_pmean[seg][b][d0]     = s0;
    g_pmean[seg][b][d0 + 1] = s1;
    g_pmean[seg][b][d0 + 2] = s2;
    g_pmean[seg][b][d0 + 3] = s3;
}

// ---------------- 2) tensor-core Gram (R14, validated) ----------------------
__global__ void __launch_bounds__(256) gram_mma(const __nv_bfloat16* __restrict__ xb) {
    int t  = blockIdx.x / SPLIT;
    int bz = blockIdx.x - t * SPLIT;
    int ti = 0;
    while ((ti + 1) * (ti + 2) / 2 <= t) ti++;
    int tj = t - ti * (ti + 1) / 2;
    int dtile = ti * 128;
    int etile = tj * 128;

    __shared__ __nv_bfloat16 As[3][32][128];
    __shared__ __nv_bfloat16 Bs[3][32][128];

    int tid  = threadIdx.x;
    int lane = tid & 31;
    int warp = tid >> 5;
    int m0 = (warp >> 2) * 64;
    int n0 = (warp & 3) * 32;

    const __nv_bfloat16* xbase = xb + (size_t)bz * Tn * Dn;

    float acc[4][4][4];
#pragma unroll
    for (int a = 0; a < 4; a++)
#pragma unroll
        for (int b = 0; b < 4; b++)
#pragma unroll
            for (int c = 0; c < 4; c++) acc[a][b][c] = 0.f;

    auto issue = [&](int it, int stg) {
#pragma unroll
        for (int rep = 0; rep < 2; rep++) {
            int l    = tid + rep * 256;
            int row  = l >> 4;
            int ch   = l & 15;
            int chs  = ch ^ (row & 7);
            const __nv_bfloat16* gA = xbase + (size_t)(it * 32 + row) * Dn + dtile + ch * 8;
            const __nv_bfloat16* gB = xbase + (size_t)(it * 32 + row) * Dn + etile + ch * 8;
            uint32_t sA = smem_u32(&As[stg][row][chs * 8]);
            uint32_t sB = smem_u32(&Bs[stg][row][chs * 8]);
            asm volatile("cp.async.cg.shared.global [%0], [%1], 16;" :: "r"(sA), "l"(gA));
            asm volatile("cp.async.cg.shared.global [%0], [%1], 16;" :: "r"(sB), "l"(gB));
        }
    };

    issue(0, 0);
    asm volatile("cp.async.commit_group;");
    issue(1, 1);
    asm volatile("cp.async.commit_group;");

    int stg = 0;
    for (int it = 0; it < NIT; it++) {
        if (it + 2 < NIT) {
            issue(it + 2, (it + 2) % 3);
            asm volatile("cp.async.commit_group;");
            asm volatile("cp.async.wait_group 2;");
        } else if (it + 1 < NIT) {
            asm volatile("cp.async.wait_group 1;");
        } else {
            asm volatile("cp.async.wait_group 0;");
        }
        __syncthreads();

#pragma unroll
        for (int ks = 0; ks < 2; ks++) {
            uint32_t a[4][4];
            uint32_t bfr[2][4];
#pragma unroll
            for (int mi = 0; mi < 4; mi++) {
                int krow = ks * 16 + (lane & 7) + ((lane & 16) ? 8 : 0);
                int ch   = (m0 >> 3) + mi * 2 + ((lane >> 3) & 1);
                int chs  = ch ^ (krow & 7);
                uint32_t addr = smem_u32(&As[stg][krow][chs * 8]);
                asm volatile("ldmatrix.sync.aligned.m8n8.x4.trans.shared.b16 {%0,%1,%2,%3}, [%4];"
                             : "=r"(a[mi][0]), "=r"(a[mi][1]), "=r"(a[mi][2]), "=r"(a[mi][3])
                             : "r"(addr));
            }
#pragma unroll
            for (int pb = 0; pb < 2; pb++) {
                int krow = ks * 16 + (lane & 7) + ((lane & 8) ? 8 : 0);
                int ch   = (n0 >> 3) + pb * 2 + ((lane >> 4) & 1);
                int chs  = ch ^ (krow & 7);
                uint32_t addr = smem_u32(&Bs[stg][krow][chs * 8]);
                asm volatile("ldmatrix.sync.aligned.m8n8.x4.trans.shared.b16 {%0,%1,%2,%3}, [%4];"
                             : "=r"(bfr[pb][0]), "=r"(bfr[pb][1]), "=r"(bfr[pb][2]), "=r"(bfr[pb][3])
                             : "r"(addr));
            }
#pragma unroll
            for (int mi = 0; mi < 4; mi++)
#pragma unroll
                for (int nb = 0; nb < 4; nb++) {
                    uint32_t b0 = bfr[nb >> 1][(nb & 1) * 2];
                    uint32_t b1 = bfr[nb >> 1][(nb & 1) * 2 + 1];
                    asm volatile(
                        "mma.sync.aligned.m16n8k16.row.col.f32.bf16.bf16.f32 "
                        "{%0,%1,%2,%3}, {%4,%5,%6,%7}, {%8,%9}, {%0,%1,%2,%3};"
                        : "+f"(acc[mi][nb][0]), "+f"(acc[mi][nb][1]),
                          "+f"(acc[mi][nb][2]), "+f"(acc[mi][nb][3])
                        : "r"(a[mi][0]), "r"(a[mi][1]), "r"(a[mi][2]), "r"(a[mi][3]),
                          "r"(b0), "r"(b1));
                }
        }
        __syncthreads();
        stg = (stg + 1 == 3) ? 0 : stg + 1;
    }

    float* gp = g_Gpart[bz];
    int g  = lane >> 2;
    int tg = lane & 3;
#pragma unroll
    for (int mi = 0; mi < 4; mi++)
#pragma unroll
        for (int nb = 0; nb < 4; nb++) {
            int row = dtile + m0 + mi * 16 + g;
            int col = etile + n0 + nb * 8 + tg * 2;
            *(float2*)&gp[(size_t)row * Dn + col]       = make_float2(acc[mi][nb][0], acc[mi][nb][1]);
            *(float2*)&gp[(size_t)(row + 8) * Dn + col] = make_float2(acc[mi][nb][2], acc[mi][nb][3]);
        }
}

// ---------------- warp-shuffle 32x32 Cholesky factor (triangular) -----------
__device__ __forceinline__ void factor32_warp(float* s, int lane) {
    float a[32];
#pragma unroll
    for (int i = 0; i < 32; i++) a[i] = (i >= lane) ? s[i * 33 + lane] : 0.f;
#pragma unroll
    for (int j = 0; j < 32; j++) {
        float pivot = __shfl_sync(0xffffffffu, a[j], j);
        float rinv  = rsqrtf(pivot);
        float lej = 0.f;
#pragma unroll
        for (int i = j; i < 32; i++) {
            float lij = __shfl_sync(0xffffffffu, a[i], j) * rinv;
            if (i == lane) lej = lij;
            if (lane == j) a[i] = lij;
            else if (lane > j && i >= lane) a[i] -= lij * lej;
        }
    }
#pragma unroll
    for (int i = 0; i < 32; i++)
        if (i >= lane) s[i * 33 + lane] = a[i];
}

// per-row triangular forward substitution: solve t * D^T, D lower in smem
__device__ __forceinline__ void trsm_row(float* S, int rr, const float* D,
                                         const float* dinv) {
    float t[32];
#pragma unroll
    for (int j = 0; j < 32; j++) t[j] = S[rr * 33 + j];
#pragma unroll
    for (int j = 0; j < 32; j++) {
        float tj_ = t[j] * dinv[j];
        t[j] = tj_;
#pragma unroll
        for (int k2 = j + 1; k2 < 32; k2++)
            t[k2] -= tj_ * D[k2 * 33 + j];
    }
#pragma unroll
    for (int j = 0; j < 32; j++) S[rr * 33 + j] = t[j];
}

// ---------------- 3) persistent chol: TWO panels per barrier ----------------
__global__ void __launch_bounds__(NTHR) chol_fast(const float* __restrict__ z,
                                                  float* __restrict__ out) {
    __shared__ float Da[32 * 33], Db[32 * 33], Sba[32 * 33];
    __shared__ float Sia[32 * 33], Ska[32 * 33], Sib[32 * 33], Skb[32 * 33];
    __shared__ float dinvA[32], dinvB[32];

    unsigned phase = 0;
    int bid = blockIdx.x, tid = threadIdx.x;
    int rT = tid >> 3;            // 0..31
    int cT = (tid & 7) * 4;       // col*4

    // ---- phase A: z transpose + cov lower tiles ----
    for (int idx = bid * NTHR + tid; idx < ZB * Dn; idx += NBLK * NTHR) {
        int s = idx >> 9, e = idx & 511;
        g_zT[e * ZB + s] = z[idx];
    }
    {
        const float inv   = 1.0f / ((float)(Tn - 1) * (float)Bn);
        const float tninv = 1.0f / (float)Tn;
        for (int t = bid; t < NTILE; t += NBLK) {
            int ti = 0;
            while ((ti + 1) * (ti + 2) / 2 <= t) ti++;
            int tj = t - ti * (ti + 1) / 2;
            __syncthreads();
            for (int l = tid; l < Bn * 32; l += NTHR) {
                int b = l >> 5, rr = l & 31;
                float s1 = 0.f, s2 = 0.f;
#pragma unroll
                for (int sg = 0; sg < SEG; sg++) {
                    s1 += g_pmean[sg][b][ti * 32 + rr];
                    s2 += g_pmean[sg][b][tj * 32 + rr];
                }
                Sia[b * 33 + rr] = s1 * tninv;
                Ska[b * 33 + rr] = s2 * tninv;
            }
            __syncthreads();
            float4 gs = make_float4(0.f, 0.f, 0.f, 0.f);
            size_t gidx = (size_t)(ti * 32 + rT) * Dn + tj * 32 + cT;
#pragma unroll
            for (int g = 0; g < SPLIT; g++) {
                float4 v = *(const float4*)&g_Gpart[g][gidx];
                gs.x += v.x; gs.y += v.y; gs.z += v.z; gs.w += v.w;
            }
            float mk[4] = {0.f, 0.f, 0.f, 0.f};
#pragma unroll
            for (int b = 0; b < Bn; b++) {
                float pir = Sia[b * 33 + rT];
#pragma unroll
                for (int c = 0; c < 4; c++) mk[c] += pir * Ska[b * 33 + cT + c];
            }
            float4 res;
            res.x = (gs.x - (float)Tn * mk[0]) * inv;
            res.y = (gs.y - (float)Tn * mk[1]) * inv;
            res.z = (gs.z - (float)Tn * mk[2]) * inv;
            res.w = (gs.w - (float)Tn * mk[3]) * inv;
            *(float4*)&g_C[gidx] = res;
        }
    }
    gbar(&phase);

    // ---- 8 windows, each covering panels a=2w, b=2w+1 ----
    for (int w = 0; w < NT / 2; w++) {
        int a0 = (2 * w) * 32;
        int b0 = a0 + 32;
        int m = NT - 2 - 2 * w;               // trailing 32-strips beyond b
        int ntile = m * (m + 1) / 2;

        if (bid < ntile || bid == 0) {
            bool work = bid < ntile;
            int ti = 0, tj = 0, i0 = 0, k0 = 0;
            bool diag = false;
            if (work) {
                while ((ti + 1) * (ti + 2) / 2 <= bid) ti++;
                tj = bid - ti * (ti + 1) / 2;
                i0 = b0 + 32 + ti * 32;
                k0 = b0 + 32 + tj * 32;
                diag = (ti == tj);
            }

            // ---- 1. stage all tiles (float4 per thread each) ----
            {
                float4 v;
                v = *(const float4*)&g_C[(size_t)(a0 + rT) * Dn + a0 + cT];
                *(float4*)&Da[rT * 33 + cT] = v;   // note: 33-stride, so write scalar
            }
            // (33-stride prevents float4 smem stores from being contiguous;
            //  write elementwise instead)
            {
                float4 v = *(const float4*)&g_C[(size_t)(a0 + rT) * Dn + a0 + cT];
                Da[rT * 33 + cT] = v.x; Da[rT * 33 + cT + 1] = v.y;
                Da[rT * 33 + cT + 2] = v.z; Da[rT * 33 + cT + 3] = v.w;
                v = *(const float4*)&g_C[(size_t)(b0 + rT) * Dn + a0 + cT];
                Sba[rT * 33 + cT] = v.x; Sba[rT * 33 + cT + 1] = v.y;
                Sba[rT * 33 + cT + 2] = v.z; Sba[rT * 33 + cT + 3] = v.w;
                v = *(const float4*)&g_C[(size_t)(b0 + rT) * Dn + b0 + cT];
                Db[rT * 33 + cT] = v.x; Db[rT * 33 + cT + 1] = v.y;
                Db[rT * 33 + cT + 2] = v.z; Db[rT * 33 + cT + 3] = v.w;
                if (work) {
                    v = *(const float4*)&g_C[(size_t)(i0 + rT) * Dn + a0 + cT];
                    Sia[rT * 33 + cT] = v.x; Sia[rT * 33 + cT + 1] = v.y;
                    Sia[rT * 33 + cT + 2] = v.z; Sia[rT * 33 + cT + 3] = v.w;
                    v = *(const float4*)&g_C[(size_t)(i0 + rT) * Dn + b0 + cT];
                    Sib[rT * 33 + cT] = v.x; Sib[rT * 33 + cT + 1] = v.y;
                    Sib[rT * 33 + cT + 2] = v.z; Sib[rT * 33 + cT + 3] = v.w;
                    if (!diag) {
                        v = *(const float4*)&g_C[(size_t)(k0 + rT) * Dn + a0 + cT];
                        Ska[rT * 33 + cT] = v.x; Ska[rT * 33 + cT + 1] = v.y;
                        Ska[rT * 33 + cT + 2] = v.z; Ska[rT * 33 + cT + 3] = v.w;
                        v = *(const float4*)&g_C[(size_t)(k0 + rT) * Dn + b0 + cT];
                        Skb[rT * 33 + cT] = v.x; Skb[rT * 33 + cT + 1] = v.y;
                        Skb[rT * 33 + cT + 2] = v.z; Skb[rT * 33 + cT + 3] = v.w;
                    }
                }
            }
            __syncthreads();

            // ---- 2. factor Da ----
            if (tid < 32) {
                factor32_warp(Da, tid);
                dinvA[tid] = 1.0f / Da[tid * 33 + tid];
            }
            __syncthreads();

            // ---- 3. TRSM vs Da: Sba (32 rows), Sia (32), Ska (32) ----
            if (tid < 32)                 trsm_row(Sba, tid, Da, dinvA);
            else if (work && tid < 64)    trsm_row(Sia, tid - 32, Da, dinvA);
            else if (work && !diag && tid < 96) trsm_row(Ska, tid - 64, Da, dinvA);
            __syncthreads();

            // publish: block0 -> La (lower) + Lba (full); diag block -> Sia
            if (bid == 0) {
                for (int l = tid; l < 1024; l += NTHR) {
                    int ii = l >> 5, kk = l & 31;
                    if (kk <= ii) g_L[(size_t)(a0 + ii) * Dn + a0 + kk] = Da[ii * 33 + kk];
                    g_L[(size_t)(b0 + ii) * Dn + a0 + kk] = Sba[ii * 33 + kk];
                }
            }
            if (work && diag) {
                for (int l = tid; l < 1024; l += NTHR) {
                    int ii = l >> 5, kk = l & 31;
                    g_L[(size_t)(i0 + ii) * Dn + a0 + kk] = Sia[ii * 33 + kk];
                }
            }

            // ---- 4. Db -= Lba Lba^T ; factor Db ----
            {
                float acc[4] = {0.f, 0.f, 0.f, 0.f};
#pragma unroll 8
                for (int mm = 0; mm < 32; mm++) {
                    float x = Sba[rT * 33 + mm];
#pragma unroll
                    for (int c = 0; c < 4; c++) acc[c] += x * Sba[(cT + c) * 33 + mm];
                }
                __syncthreads();
#pragma unroll
                for (int c = 0; c < 4; c++) Db[rT * 33 + cT + c] -= acc[c];
            }
            __syncthreads();
            if (tid < 32) {
                factor32_warp(Db, tid);
                dinvB[tid] = 1.0f / Db[tid * 33 + tid];
            }
            __syncthreads();
            if (bid == 0) {
                for (int l = tid; l < 1024; l += NTHR) {
                    int ii = l >> 5, kk = l & 31;
                    if (kk <= ii) g_L[(size_t)(b0 + ii) * Dn + b0 + kk] = Db[ii * 33 + kk];
                }
            }

            if (work) {
                // ---- 5. corrections: S·b -= S·a * Lba^T ; TRSM vs Db ----
                {
                    float acc[4] = {0.f, 0.f, 0.f, 0.f};
#pragma unroll 8
                    for (int mm = 0; mm < 32; mm++) {
                        float x = Sia[rT * 33 + mm];
#pragma unroll
                        for (int c = 0; c < 4; c++) acc[c] += x * Sba[(cT + c) * 33 + mm];
                    }
#pragma unroll
                    for (int c = 0; c < 4; c++) Sib[rT * 33 + cT + c] -= acc[c];
                    if (!diag) {
                        float ack[4] = {0.f, 0.f, 0.f, 0.f};
#pragma unroll 8
                        for (int mm = 0; mm < 32; mm++) {
                            float x = Ska[rT * 33 + mm];
#pragma unroll
                            for (int c = 0; c < 4; c++) ack[c] += x * Sba[(cT + c) * 33 + mm];
                        }
#pragma unroll
                        for (int c = 0; c < 4; c++) Skb[rT * 33 + cT + c] -= ack[c];
                    }
                }
                __syncthreads();
                if (tid < 32)              trsm_row(Sib, tid, Db, dinvB);
                else if (!diag && tid < 64) trsm_row(Skb, tid - 32, Db, dinvB);
                __syncthreads();

                if (diag) {
                    for (int l = tid; l < 1024; l += NTHR) {
                        int ii = l >> 5, kk = l & 31;
                        g_L[(size_t)(i0 + ii) * Dn + b0 + kk] = Sib[ii * 33 + kk];
                    }
                }

                // ---- 6. fused double SYRK: C(i,k) -= Sia Ska^T + Sib Skb^T --
                const float* PKa = diag ? Sia : Ska;
                const float* PKb = diag ? Sib : Skb;
                float acc[4] = {0.f, 0.f, 0.f, 0.f};
#pragma unroll 8
                for (int mm = 0; mm < 32; mm++) {
                    float xa = Sia[rT * 33 + mm];
                    float xb = Sib[rT * 33 + mm];
#pragma unroll
                    for (int c = 0; c < 4; c++)
                        acc[c] += xa * PKa[(cT + c) * 33 + mm] + xb * PKb[(cT + c) * 33 + mm];
                }
                {
                    float4 cv = *(const float4*)&g_C[(size_t)(i0 + rT) * Dn + k0 + cT];
                    cv.x -= acc[0]; cv.y -= acc[1]; cv.z -= acc[2]; cv.w -= acc[3];
                    *(float4*)&g_C[(size_t)(i0 + rT) * Dn + k0 + cT] = cv;
                }
            }
        }
        gbar(&phase);
    }

    // ---- output: warp per d ----
    {
        int lane = tid & 31;
        int d    = bid * 8 + (tid >> 5);
        if (d < Dn) {
            float gs = 0.f;
#pragma unroll
            for (int q = 0; q < 16; q++) {
                int pr = lane * 16 + q;
                gs += g_pmean[pr >> 5][pr & 31][d];
            }
#pragma unroll
            for (int off = 16; off > 0; off >>= 1)
                gs += __shfl_xor_sync(0xffffffffu, gs, off);
            float acc = gs * (1.0f / ((float)Tn * (float)Bn));
            const float* Lrow = g_L + (size_t)d * Dn;
            float a0 = 0.f, a1 = 0.f, a2 = 0.f, a3 = 0.f;
            int e = 0;
            for (; e + 3 <= d; e += 4) {
                a0 += g_zT[(e + 0) * ZB + lane] * Lrow[e + 0];
                a1 += g_zT[(e + 1) * ZB + lane] * Lrow[e + 1];
                a2 += g_zT[(e + 2) * ZB + lane] * Lrow[e + 2];
                a3 += g_zT[(e + 3) * ZB + lane] * Lrow[e + 3];
            }
            for (; e <= d; e++) a0 += g_zT[e * ZB + lane] * Lrow[e];
            acc += (a0 + a1) + (a2 + a3);
            out[(size_t)lane * Dn + d] = acc;
        }
    }
}

// ---------------- launch -----------------------------------------------------
extern "C" void kernel_launch(void* const* d_in, const int* in_sizes, int n_in,
                              void* d_out, int out_size) {
    const float* x = (const float*)d_in[0];
    const float* z = (const float*)d_in[1];
    if (in_sizes[0] != Bn * Tn * Dn) { x = (const float*)d_in[1]; z = (const float*)d_in[0]; }
    float* out = (float*)d_out;

    conv_mean<<<dim3(1, Bn, SEG), 128>>>(x);

    __nv_bfloat16* xcb;
    cudaGetSymbolAddress((void**)&xcb, g_xcb);
    gram_mma<<<GTILE * SPLIT, 256>>>(xcb);

    chol_fast<<<NBLK, NTHR>>>(z, out);
}

// round 16
// speedup vs baseline: 1.2940x; 1.2940x over previous
#include <cuda_runtime.h>
#include <cuda_bf16.h>
#include <cstdint>
#include <math.h>

#define Bn 32
#define Tn 2048
#define Dn 512
#define ZB 32
#define SPLIT 64                    // K chunks of 1024 rows (flattened 65536)
#define KCH 1024
#define NITG (KCH / 32)             // 32 gram iters per chunk
#define SEG 32
#define NT 16
#define NTILE (NT * (NT + 1) / 2)   // 136 lower cov tiles
#define NBLK 120
#define NTHR 256
#define GTILE 10                    // lower 128x128 tiles of 4x4

// ---------------- static scratch ----------------
__device__ float g_pmean[SEG][Bn][Dn];
__device__ float g_zT[Dn * ZB];                 // z transposed [e][s]
__device__ __nv_bfloat16 g_xcb[(size_t)Bn * Tn * Dn];
__device__ float g_Gpart[SPLIT][Dn * Dn];
__device__ float g_C[Dn * Dn];                  // raw updated covariance (lower tiles)
__device__ float g_L[Dn * Dn];                  // Cholesky factor L (lower)
__device__ unsigned g_bar8[8 * 32];             // distributed barrier counters

__device__ __forceinline__ uint32_t smem_u32(const void* p) {
    return (uint32_t)__cvta_generic_to_shared(p);
}

// grid barrier: distributed arrival (8 lines), relaxed poll, single acquire fence
__device__ __forceinline__ void gbar(unsigned* phase) {
    __syncthreads();
    if (threadIdx.x == 0) {
        unsigned target = (++(*phase)) * NBLK;
        asm volatile("red.release.gpu.add.u32 [%0], 1;"
                     :: "l"(&g_bar8[(blockIdx.x & 7) * 32]) : "memory");
        unsigned s;
        do {
            s = 0;
#pragma unroll
            for (int c = 0; c < 8; c++) {
                unsigned v;
                asm volatile("ld.relaxed.gpu.u32 %0, [%1];"
                             : "=r"(v) : "l"(&g_bar8[c * 32]) : "memory");
                s += v;
            }
        } while (s < target);
        asm volatile("fence.acq_rel.gpu;" ::: "memory");
    }
    __syncthreads();
}

// ---------------- 1) fused partial means + bf16 convert (float4) ------------
__global__ void conv_mean(const float* __restrict__ x) {
    int b   = blockIdx.y;
    int seg = blockIdx.z;
    int tid = threadIdx.x;                    // 128
    int d0  = tid * 4;
    if (b == 0 && seg == 0 && tid < 8) g_bar8[tid * 32] = 0u;
    size_t base = ((size_t)b * Tn + (size_t)seg * (Tn / SEG)) * Dn + d0;
    float s0 = 0.f, s1 = 0.f, s2 = 0.f, s3 = 0.f;
#pragma unroll 8
    for (int t = 0; t < Tn / SEG; t++) {
        float4 v = *(const float4*)(x + base + (size_t)t * Dn);
        s0 += v.x; s1 += v.y; s2 += v.z; s3 += v.w;
        __nv_bfloat162 h0, h1;
        h0.x = __float2bfloat16_rn(v.x);
        h0.y = __float2bfloat16_rn(v.y);
        h1.x = __float2bfloat16_rn(v.z);
        h1.y = __float2bfloat16_rn(v.w);
        uint2 packed;
        packed.x = *(uint32_t*)&h0;
        packed.y = *(uint32_t*)&h1;
        *(uint2*)(g_xcb + base + (size_t)t * Dn) = packed;
    }
    g_pmean[seg][b][d0]     = s0;
    g_pmean[seg][b][d0 + 1] = s1;
    g_pmean[seg][b][d0 + 2] = s2;
    g_pmean[seg][b][d0 + 3] = s3;
}

// ---------------- 2) tensor-core Gram: 64 K-chunks x 10 tiles ---------------
__global__ void __launch_bounds__(256) gram_mma(const __nv_bfloat16* __restrict__ xb) {
    int t  = blockIdx.x / SPLIT;
    int c  = blockIdx.x - t * SPLIT;          // K chunk
    int ti = 0;
    while ((ti + 1) * (ti + 2) / 2 <= t) ti++;
    int tj = t - ti * (ti + 1) / 2;
    int dtile = ti * 128;
    int etile = tj * 128;

    __shared__ __nv_bfloat16 As[3][32][128];
    __shared__ __nv_bfloat16 Bs[3][32][128];

    int tid  = threadIdx.x;
    int lane = tid & 31;
    int warp = tid >> 5;
    int m0 = (warp >> 2) * 64;
    int n0 = (warp & 3) * 32;

    const __nv_bfloat16* xbase = xb + (size_t)c * KCH * Dn;

    float acc[4][4][4];
#pragma unroll
    for (int a = 0; a < 4; a++)
#pragma unroll
        for (int b = 0; b < 4; b++)
#pragma unroll
            for (int cc = 0; cc < 4; cc++) acc[a][b][cc] = 0.f;

    auto issue = [&](int it, int stg) {
#pragma unroll
        for (int rep = 0; rep < 2; rep++) {
            int l    = tid + rep * 256;
            int row  = l >> 4;
            int ch   = l & 15;
            int chs  = ch ^ (row & 7);
            const __nv_bfloat16* gA = xbase + (size_t)(it * 32 + row) * Dn + dtile + ch * 8;
            const __nv_bfloat16* gB = xbase + (size_t)(it * 32 + row) * Dn + etile + ch * 8;
            uint32_t sA = smem_u32(&As[stg][row][chs * 8]);
            uint32_t sB = smem_u32(&Bs[stg][row][chs * 8]);
            asm volatile("cp.async.cg.shared.global [%0], [%1], 16;" :: "r"(sA), "l"(gA));
            asm volatile("cp.async.cg.shared.global [%0], [%1], 16;" :: "r"(sB), "l"(gB));
        }
    };

    issue(0, 0);
    asm volatile("cp.async.commit_group;");
    issue(1, 1);
    asm volatile("cp.async.commit_group;");

    int stg = 0;
    for (int it = 0; it < NITG; it++) {
        if (it + 2 < NITG) {
            issue(it + 2, (it + 2) % 3);
            asm volatile("cp.async.commit_group;");
            asm volatile("cp.async.wait_group 2;");
        } else if (it + 1 < NITG) {
            asm volatile("cp.async.wait_group 1;");
        } else {
            asm volatile("cp.async.wait_group 0;");
        }
        __syncthreads();

#pragma unroll
        for (int ks = 0; ks < 2; ks++) {
            uint32_t a[4][4];
            uint32_t bfr[2][4];
#pragma unroll
            for (int mi = 0; mi < 4; mi++) {
                int krow = ks * 16 + (lane & 7) + ((lane & 16) ? 8 : 0);
                int ch   = (m0 >> 3) + mi * 2 + ((lane >> 3) & 1);
                int chs  = ch ^ (krow & 7);
                uint32_t addr = smem_u32(&As[stg][krow][chs * 8]);
                asm volatile("ldmatrix.sync.aligned.m8n8.x4.trans.shared.b16 {%0,%1,%2,%3}, [%4];"
                             : "=r"(a[mi][0]), "=r"(a[mi][1]), "=r"(a[mi][2]), "=r"(a[mi][3])
                             : "r"(addr));
            }
#pragma unroll
            for (int pb = 0; pb < 2; pb++) {
                int krow = ks * 16 + (lane & 7) + ((lane & 8) ? 8 : 0);
                int ch   = (n0 >> 3) + pb * 2 + ((lane >> 4) & 1);
                int chs  = ch ^ (krow & 7);
                uint32_t addr = smem_u32(&Bs[stg][krow][chs * 8]);
                asm volatile("ldmatrix.sync.aligned.m8n8.x4.trans.shared.b16 {%0,%1,%2,%3}, [%4];"
                             : "=r"(bfr[pb][0]), "=r"(bfr[pb][1]), "=r"(bfr[pb][2]), "=r"(bfr[pb][3])
                             : "r"(addr));
            }
#pragma unroll
            for (int mi = 0; mi < 4; mi++)
#pragma unroll
                for (int nb = 0; nb < 4; nb++) {
                    uint32_t b0 = bfr[nb >> 1][(nb & 1) * 2];
                    uint32_t b1 = bfr[nb >> 1][(nb & 1) * 2 + 1];
                    asm volatile(
                        "mma.sync.aligned.m16n8k16.row.col.f32.bf16.bf16.f32 "
                        "{%0,%1,%2,%3}, {%4,%5,%6,%7}, {%8,%9}, {%0,%1,%2,%3};"
                        : "+f"(acc[mi][nb][0]), "+f"(acc[mi][nb][1]),
                          "+f"(acc[mi][nb][2]), "+f"(acc[mi][nb][3])
                        : "r"(a[mi][0]), "r"(a[mi][1]), "r"(a[mi][2]), "r"(a[mi][3]),
                          "r"(b0), "r"(b1));
                }
        }
        __syncthreads();
        stg = (stg + 1 == 3) ? 0 : stg + 1;
    }

    float* gp = g_Gpart[c];
    int g  = lane >> 2;
    int tg = lane & 3;
#pragma unroll
    for (int mi = 0; mi < 4; mi++)
#pragma unroll
        for (int nb = 0; nb < 4; nb++) {
            int row = dtile + m0 + mi * 16 + g;
            int col = etile + n0 + nb * 8 + tg * 2;
            *(float2*)&gp[(size_t)row * Dn + col]       = make_float2(acc[mi][nb][0], acc[mi][nb][1]);
            *(float2*)&gp[(size_t)(row + 8) * Dn + col] = make_float2(acc[mi][nb][2], acc[mi][nb][3]);
        }
}

// ---------------- warp-shuffle 32x32 Cholesky factor (triangular) -----------
__device__ __forceinline__ void factor32_warp(float* s, int lane) {
    float a[32];
#pragma unroll
    for (int i = 0; i < 32; i++) a[i] = (i >= lane) ? s[i * 33 + lane] : 0.f;
#pragma unroll
    for (int j = 0; j < 32; j++) {
        float pivot = __shfl_sync(0xffffffffu, a[j], j);
        float rinv  = rsqrtf(pivot);
        float lej = 0.f;
#pragma unroll
        for (int i = j; i < 32; i++) {
            float lij = __shfl_sync(0xffffffffu, a[i], j) * rinv;
            if (i == lane) lej = lij;
            if (lane == j) a[i] = lij;
            else if (lane > j && i >= lane) a[i] -= lij * lej;
        }
    }
#pragma unroll
    for (int i = 0; i < 32; i++)
        if (i >= lane) s[i * 33 + lane] = a[i];
}

// ---------------- 3) persistent chol: 1 barrier per panel (R14, validated) --
__global__ void __launch_bounds__(NTHR) chol_fast(const float* __restrict__ z,
                                                  float* __restrict__ out) {
    __shared__ float Pi[32 * 33];
    __shared__ float Pk[32 * 33];
    __shared__ float Dg[32 * 33];
    __shared__ float sDinv[32];

    unsigned phase = 0;
    int bid = blockIdx.x, tid = threadIdx.x;

    // ---- phase A: z transpose + cov lower tiles (bmean from g_pmean) ----
    for (int idx = bid * NTHR + tid; idx < ZB * Dn; idx += NBLK * NTHR) {
        int s = idx >> 9, e = idx & 511;
        g_zT[e * ZB + s] = z[idx];
    }
    {
        const float inv   = 1.0f / ((float)(Tn - 1) * (float)Bn);
        const float tninv = 1.0f / (float)Tn;
        int r  = tid >> 3;
        int cb = (tid & 7) * 4;
        for (int t = bid; t < NTILE; t += NBLK) {
            int ti = 0;
            while ((ti + 1) * (ti + 2) / 2 <= t) ti++;
            int tj = t - ti * (ti + 1) / 2;
            __syncthreads();
            for (int l = tid; l < Bn * 32; l += NTHR) {
                int b = l >> 5, rr = l & 31;
                float s1 = 0.f, s2 = 0.f;
#pragma unroll
                for (int sg = 0; sg < SEG; sg++) {
                    s1 += g_pmean[sg][b][ti * 32 + rr];
                    s2 += g_pmean[sg][b][tj * 32 + rr];
                }
                Pi[b * 33 + rr] = s1 * tninv;
                Pk[b * 33 + rr] = s2 * tninv;
            }
            __syncthreads();
            float4 gs = make_float4(0.f, 0.f, 0.f, 0.f);
            size_t gidx = (size_t)(ti * 32 + r) * Dn + tj * 32 + cb;
#pragma unroll 16
            for (int g = 0; g < SPLIT; g++) {
                float4 v = *(const float4*)&g_Gpart[g][gidx];
                gs.x += v.x; gs.y += v.y; gs.z += v.z; gs.w += v.w;
            }
            float mk[4] = {0.f, 0.f, 0.f, 0.f};
#pragma unroll
            for (int b = 0; b < Bn; b++) {
                float pir = Pi[b * 33 + r];
#pragma unroll
                for (int c = 0; c < 4; c++) mk[c] += pir * Pk[b * 33 + cb + c];
            }
            float4 res;
            res.x = (gs.x - (float)Tn * mk[0]) * inv;
            res.y = (gs.y - (float)Tn * mk[1]) * inv;
            res.z = (gs.z - (float)Tn * mk[2]) * inv;
            res.w = (gs.w - (float)Tn * mk[3]) * inv;
            *(float4*)&g_C[gidx] = res;
        }
    }
    gbar(&phase);

    // ---- panels: each block factors diag locally; one barrier per panel ----
    int rT = tid >> 3;            // 0..31 (row for float4 ops)
    int cT = (tid & 7) * 4;       // col*4
    for (int p = 0; p < NT; p++) {
        int j0 = p * 32;
        int m = NT - 1 - p;
        int ntile = m * (m + 1) / 2;

        if (bid < ntile || bid == 0) {
            // diag load (1 LDG.128 per thread) + local factor
            {
                float4 v = *(const float4*)&g_C[(size_t)(j0 + rT) * Dn + j0 + cT];
                Dg[rT * 33 + cT]     = v.x;
                Dg[rT * 33 + cT + 1] = v.y;
                Dg[rT * 33 + cT + 2] = v.z;
                Dg[rT * 33 + cT + 3] = v.w;
            }
            __syncthreads();
            if (tid < 32) {
                factor32_warp(Dg, tid);
                sDinv[tid] = 1.0f / Dg[tid * 33 + tid];
            }
            __syncthreads();

            // block 0 writes diag L
            if (bid == 0) {
                for (int l = tid; l < 1024; l += NTHR) {
                    int ii = l >> 5, kk = l & 31;
                    if (kk <= ii) g_L[(size_t)(j0 + ii) * Dn + j0 + kk] = Dg[ii * 33 + kk];
                }
            }

            if (bid < ntile) {
                int ti = 0;
                while ((ti + 1) * (ti + 2) / 2 <= bid) ti++;
                int tj = bid - ti * (ti + 1) / 2;
                int i0 = (p + 1 + ti) * 32;
                int k0 = (p + 1 + tj) * 32;
                bool diag = (ti == tj);

                // stage raw strips (float4)
                {
                    float4 v = *(const float4*)&g_C[(size_t)(i0 + rT) * Dn + j0 + cT];
                    Pi[rT * 33 + cT]     = v.x;
                    Pi[rT * 33 + cT + 1] = v.y;
                    Pi[rT * 33 + cT + 2] = v.z;
                    Pi[rT * 33 + cT + 3] = v.w;
                    if (!diag) {
                        float4 w = *(const float4*)&g_C[(size_t)(k0 + rT) * Dn + j0 + cT];
                        Pk[rT * 33 + cT]     = w.x;
                        Pk[rT * 33 + cT + 1] = w.y;
                        Pk[rT * 33 + cT + 2] = w.z;
                        Pk[rT * 33 + cT + 3] = w.w;
                    }
                }
                __syncthreads();

                // local TRSM (triangular forward substitution), rows 0..63
                int nrows = diag ? 32 : 64;
                if (tid < nrows) {
                    float* S = (tid < 32) ? Pi : Pk;
                    int rr = tid & 31;
                    float t[32];
#pragma unroll
                    for (int j = 0; j < 32; j++) t[j] = S[rr * 33 + j];
#pragma unroll
                    for (int j = 0; j < 32; j++) {
                        float tj_ = t[j] * sDinv[j];
                        t[j] = tj_;
#pragma unroll
                        for (int k2 = j + 1; k2 < 32; k2++)
                            t[k2] -= tj_ * Dg[k2 * 33 + j];
                    }
#pragma unroll
                    for (int j = 0; j < 32; j++) S[rr * 33 + j] = t[j];
                }
                __syncthreads();

                // (i,i) block publishes strip i of L
                if (diag) {
                    for (int l = tid; l < 1024; l += NTHR) {
                        int rr = l >> 5, cc = l & 31;
                        g_L[(size_t)(i0 + rr) * Dn + j0 + cc] = Pi[rr * 33 + cc];
                    }
                }

                // SYRK: g_C(i,k) -= Pi * Pk^T (full square, float4 RMW)
                const float* PK = diag ? Pi : Pk;
                float acc[4] = {0.f, 0.f, 0.f, 0.f};
#pragma unroll 8
                for (int mm = 0; mm < 32; mm++) {
                    float a = Pi[rT * 33 + mm];
#pragma unroll
                    for (int c = 0; c < 4; c++) acc[c] += a * PK[(cT + c) * 33 + mm];
                }
                {
                    float4 cv = *(const float4*)&g_C[(size_t)(i0 + rT) * Dn + k0 + cT];
                    cv.x -= acc[0]; cv.y -= acc[1]; cv.z -= acc[2]; cv.w -= acc[3];
                    *(float4*)&g_C[(size_t)(i0 + rT) * Dn + k0 + cT] = cv;
                }
            }
        }
        gbar(&phase);
    }

    // ---- output: warp per d. gmean computed from g_pmean via shfl-reduce ---
    {
        int lane = tid & 31;
        int d    = bid * 8 + (tid >> 5);
        if (d < Dn) {
            float gs = 0.f;
#pragma unroll
            for (int q = 0; q < 32; q++) {
                int pr = lane * 32 + q;
                gs += g_pmean[pr >> 5][pr & 31][d];
            }
#pragma unroll
            for (int off = 16; off > 0; off >>= 1)
                gs += __shfl_xor_sync(0xffffffffu, gs, off);
            float acc = gs * (1.0f / ((float)Tn * (float)Bn));
            const float* Lrow = g_L + (size_t)d * Dn;
            float a0 = 0.f, a1 = 0.f, a2 = 0.f, a3 = 0.f;
            int e = 0;
            for (; e + 3 <= d; e += 4) {
                a0 += g_zT[(e + 0) * ZB + lane] * Lrow[e + 0];
                a1 += g_zT[(e + 1) * ZB + lane] * Lrow[e + 1];
                a2 += g_zT[(e + 2) * ZB + lane] * Lrow[e + 2];
                a3 += g_zT[(e + 3) * ZB + lane] * Lrow[e + 3];
            }
            for (; e <= d; e++) a0 += g_zT[e * ZB + lane] * Lrow[e];
            acc += (a0 + a1) + (a2 + a3);
            out[(size_t)lane * Dn + d] = acc;
        }
    }
}

// ---------------- launch -----------------------------------------------------
extern "C" void kernel_launch(void* const* d_in, const int* in_sizes, int n_in,
                              void* d_out, int out_size) {
    const float* x = (const float*)d_in[0];
    const float* z = (const float*)d_in[1];
    if (in_sizes[0] != Bn * Tn * Dn) { x = (const float*)d_in[1]; z = (const float*)d_in[0]; }
    float* out = (float*)d_out;

    conv_mean<<<dim3(1, Bn, SEG), 128>>>(x);

    __nv_bfloat16* xcb;
    cudaGetSymbolAddress((void**)&xcb, g_xcb);
    gram_mma<<<GTILE * SPLIT, 256>>>(xcb);

    chol_fast<<<NBLK, NTHR>>>(z, out);
}